// round 1
// baseline (speedup 1.0000x reference)
#include <cuda_runtime.h>

#define B   32
#define U   32
#define TK  64
#define TDEC 64
#define D   512
#define V   50257
#define VT  128

// ---------------- scratch (device globals; no allocation allowed) ----------
__device__ float g_local_dec[B*D];
__device__ float g_dec_ua[B*D];
__device__ float g_dec_ta[B*D];
__device__ float g_target_out[B*D];
__device__ float g_h[B*D];
__device__ int   g_sel[B];
__device__ float g_logits[(long)B*V];
__device__ float g_m[B];
__device__ float g_inv_s[B];

// ---------------- helpers ----------------
__device__ __forceinline__ float ftanh(float x){
    float y; asm("tanh.approx.f32 %0, %1;" : "=f"(y) : "f"(x)); return y;
}
__device__ __forceinline__ float wsum(float v){
    #pragma unroll
    for (int o=16;o;o>>=1) v += __shfl_xor_sync(0xffffffffu, v, o);
    return v;
}
__device__ __forceinline__ float wmax(float v){
    #pragma unroll
    for (int o=16;o;o>>=1) v = fmaxf(v, __shfl_xor_sync(0xffffffffu, v, o));
    return v;
}
__device__ __forceinline__ unsigned long long pack2(float lo, float hi){
    unsigned long long r; asm("mov.b64 %0, {%1, %2};" : "=l"(r) : "f"(lo), "f"(hi)); return r;
}
__device__ __forceinline__ void unpack2(float &lo, float &hi, unsigned long long v){
    asm("mov.b64 {%0, %1}, %2;" : "=f"(lo), "=f"(hi) : "l"(v));
}
__device__ __forceinline__ void fma2(unsigned long long &d, unsigned long long a,
                                     unsigned long long b, unsigned long long c){
    asm("fma.rn.f32x2 %0, %1, %2, %3;" : "=l"(d) : "l"(a), "l"(b), "l"(c));
}

// ---------------- K1: layernorm of last decoder step ----------------
__global__ void k_ln(const float* __restrict__ tf, const float* __restrict__ g,
                     const float* __restrict__ bb){
    int b = blockIdx.x, tid = threadIdx.x;
    const float* row = tf + (b*TDEC + (TDEC-1))*D;
    float x0 = row[tid], x1 = row[tid+256];
    __shared__ float s1[256], s2[256];
    s1[tid] = x0+x1; s2[tid] = x0*x0 + x1*x1;
    __syncthreads();
    for (int o=128;o;o>>=1){
        if (tid<o){ s1[tid]+=s1[tid+o]; s2[tid]+=s2[tid+o]; }
        __syncthreads();
    }
    float mu = s1[0]*(1.0f/D);
    float var = s2[0]*(1.0f/D) - mu*mu;
    float r = rsqrtf(var + 1e-5f);
    g_local_dec[b*D+tid]     = (x0-mu)*r*g[tid]     + bb[tid];
    g_local_dec[b*D+tid+256] = (x1-mu)*r*g[tid+256] + bb[tid+256];
}

// ---------------- K2: dec projections (local_dec @ Wp.T + bp) ----------------
__global__ void k_proj(const float* __restrict__ ua_Wp, const float* __restrict__ ua_bp,
                       const float* __restrict__ ta_Wp, const float* __restrict__ ta_bp){
    int b = blockIdx.y;
    int which = blockIdx.z;
    const float* W    = which ? ta_Wp : ua_Wp;
    const float* bias = which ? ta_bp : ua_bp;
    float* outp       = which ? g_dec_ta : g_dec_ua;
    int warp = threadIdx.x >> 5, lane = threadIdx.x & 31;
    int d = blockIdx.x*8 + warp;
    const float4* wrow = (const float4*)(W + (long)d*D);
    const float4* t    = (const float4*)(g_local_dec + b*D);
    float acc = 0.f;
    #pragma unroll
    for (int i=0;i<4;i++){
        float4 w4 = wrow[i*32 + lane];
        float4 t4 = t[i*32 + lane];
        acc += w4.x*t4.x + w4.y*t4.y + w4.z*t4.z + w4.w*t4.w;
    }
    acc = wsum(acc);
    if (!lane) outp[b*D + d] = acc + bias[d];
}

// ---------------- K3: utterance attention + argmax + p_gen ----------------
__global__ void k_uatt(const float* __restrict__ enc, const float* __restrict__ umask,
                       const float* __restrict__ cov, const float* __restrict__ ua_wc,
                       const float* __restrict__ ua_v, const float* __restrict__ pgen_W,
                       const float* __restrict__ pgen_b,
                       float* __restrict__ o_ucov, float* __restrict__ o_pgen,
                       float* __restrict__ o_uidx){
    int b = blockIdx.x; int tid = threadIdx.x;
    int warp = tid>>5, lane = tid&31;
    __shared__ float s_scores[U], s_attn[U], s_red[256];

    float4 dec4[4], wc4[4], v4[4];
    #pragma unroll
    for (int i=0;i<4;i++){
        int d = i*128 + lane*4;
        dec4[i] = *(const float4*)(g_dec_ua + b*D + d);
        wc4[i]  = *(const float4*)(ua_wc + d);
        v4[i]   = *(const float4*)(ua_v + d);
    }
    #pragma unroll
    for (int uu=0; uu<4; uu++){
        int u = warp + uu*8;
        float c = cov[b*U + u];
        const float4* e = (const float4*)(enc + (long)(b*U + u)*D);
        float acc = 0.f;
        #pragma unroll
        for (int i=0;i<4;i++){
            float4 x = e[i*32 + lane];
            acc += ftanh(x.x + dec4[i].x + c*wc4[i].x) * v4[i].x;
            acc += ftanh(x.y + dec4[i].y + c*wc4[i].y) * v4[i].y;
            acc += ftanh(x.z + dec4[i].z + c*wc4[i].z) * v4[i].z;
            acc += ftanh(x.w + dec4[i].w + c*wc4[i].w) * v4[i].w;
        }
        acc = wsum(acc);
        if (!lane) s_scores[u] = acc;
    }
    __syncthreads();
    if (warp == 0){
        int u = lane;
        float s = s_scores[u];
        float m = wmax(s);
        float e = expf(s - m);
        float den = wsum(e);
        float a_ = (e/den) * umask[b*U+u];
        float nf = wsum(a_);
        float attn = a_ / (nf == 0.f ? 1.f : nf);
        s_attn[u] = attn;
        o_ucov[b*U+u] = cov[b*U+u] + attn;
        // argmax (first occurrence on ties)
        float bv = attn; int bi = u;
        #pragma unroll
        for (int o=16;o;o>>=1){
            float ov = __shfl_xor_sync(0xffffffffu, bv, o);
            int   oi = __shfl_xor_sync(0xffffffffu, bi, o);
            if (ov > bv || (ov == bv && oi < bi)){ bv = ov; bi = oi; }
        }
        if (!lane){ g_sel[b] = bi; o_uidx[b] = (float)bi; }
    }
    __syncthreads();
    // u_out (for p_gen only) + p_gen partial
    float part = 0.f;
    #pragma unroll
    for (int j=0;j<2;j++){
        int d = tid + j*256;
        float acc = 0.f;
        #pragma unroll 8
        for (int u=0;u<U;u++) acc += s_attn[u] * enc[(long)(b*U+u)*D + d];
        part += pgen_W[d]*acc + pgen_W[D + d]*g_local_dec[b*D + d];
    }
    s_red[tid] = part;
    __syncthreads();
    for (int o=128;o;o>>=1){ if (tid<o) s_red[tid]+=s_red[tid+o]; __syncthreads(); }
    if (!tid){
        float z = s_red[0] + pgen_b[0];
        o_pgen[b] = 1.f/(1.f + expf(-z));
    }
}

// ---------------- K4: token attention (single-read; selected tiles reread) ----
__global__ void k_tatt(const float* __restrict__ tok, const float* __restrict__ tmask,
                       const float* __restrict__ tcov, const float* __restrict__ ta_wc,
                       const float* __restrict__ ta_v,
                       float* __restrict__ o_ntc, float* __restrict__ o_tattn){
    int u = blockIdx.x, b = blockIdx.y;
    int tid = threadIdx.x, warp = tid>>5, lane = tid&31;
    __shared__ float s_scores[TK], s_attn[TK];
    int ub = u*B + b;

    float4 dec4[4], wc4[4], v4[4];
    #pragma unroll
    for (int i=0;i<4;i++){
        int d = i*128 + lane*4;
        dec4[i] = *(const float4*)(g_dec_ta + b*D + d);
        wc4[i]  = *(const float4*)(ta_wc + d);
        v4[i]   = *(const float4*)(ta_v + d);
    }
    const float4* base = (const float4*)(tok + (long)ub*TK*D);
    #pragma unroll
    for (int tt=0; tt<8; tt++){
        int t = warp*8 + tt;
        float c = tcov[ub*TK + t];
        const float4* row = base + t*(D/4);
        float acc = 0.f;
        #pragma unroll
        for (int i=0;i<4;i++){
            float4 x = row[i*32+lane];
            acc += ftanh(x.x + dec4[i].x + c*wc4[i].x)*v4[i].x;
            acc += ftanh(x.y + dec4[i].y + c*wc4[i].y)*v4[i].y;
            acc += ftanh(x.z + dec4[i].z + c*wc4[i].z)*v4[i].z;
            acc += ftanh(x.w + dec4[i].w + c*wc4[i].w)*v4[i].w;
        }
        acc = wsum(acc);
        if (!lane) s_scores[t] = acc;
    }
    __syncthreads();
    int sel = g_sel[b];
    if (warp == 0){
        float s0 = s_scores[lane], s1 = s_scores[lane+32];
        float m = wmax(fmaxf(s0,s1));
        float e0 = expf(s0-m), e1 = expf(s1-m);
        float den = wsum(e0+e1);
        float a0 = (e0/den)*tmask[ub*TK+lane];
        float a1 = (e1/den)*tmask[ub*TK+lane+32];
        float nf = wsum(a0+a1);
        float inv = 1.f/((nf==0.f)?1.f:nf);
        a0 *= inv; a1 *= inv;
        s_attn[lane] = a0; s_attn[lane+32] = a1;
        o_ntc[ub*TK+lane]    = tcov[ub*TK+lane]    + a0;
        o_ntc[ub*TK+lane+32] = tcov[ub*TK+lane+32] + a1;
        if (u == sel){ o_tattn[b*TK+lane] = a0; o_tattn[b*TK+lane+32] = a1; }
    }
    __syncthreads();
    if (u == sel){
        #pragma unroll
        for (int j=0;j<2;j++){
            int d = tid + j*256;
            float acc = 0.f;
            #pragma unroll 8
            for (int t=0;t<TK;t++) acc += s_attn[t]*tok[(long)ub*TK*D + t*D + d];
            g_target_out[b*D + d] = acc;
        }
    }
}

// ---------------- K5: h = concat(target_out, local_dec) @ out1_W.T + b1 -------
__global__ void k_h(const float* __restrict__ W1, const float* __restrict__ b1){
    int b = blockIdx.y;
    int warp = threadIdx.x>>5, lane = threadIdx.x&31;
    int d = blockIdx.x*8 + warp;
    const float4* w  = (const float4*)(W1 + (long)d*2*D);
    const float4* t0 = (const float4*)(g_target_out + b*D);
    const float4* t1 = (const float4*)(g_local_dec + b*D);
    float acc=0.f;
    #pragma unroll
    for (int i=0;i<4;i++){
        float4 w4 = w[i*32+lane]; float4 x = t0[i*32+lane];
        acc += w4.x*x.x + w4.y*x.y + w4.z*x.z + w4.w*x.w;
    }
    #pragma unroll
    for (int i=0;i<4;i++){
        float4 w4 = w[(i+4)*32+lane]; float4 x = t1[i*32+lane];
        acc += w4.x*x.x + w4.y*x.y + w4.z*x.z + w4.w*x.w;
    }
    acc = wsum(acc);
    if (!lane) g_h[b*D+d] = acc + b1[d];
}

// ---------------- K6: vocab GEMM (f32x2 packed FFMA) ----------------
__global__ void k_vocab(const float* __restrict__ W2, const float* __restrict__ b2){
    __shared__ float sW[VT*65];                 // 128 x 64 padded
    __shared__ unsigned long long sH[16*64];    // b-pairs x k
    int tid = threadIdx.x;
    int v0 = blockIdx.x * VT;
    int tv = tid & 63;   // v-pair slot
    int bg = tid >> 6;   // b-pair group (4 pairs each)
    int vl = tv*2;

    unsigned long long acc[2][4];
    #pragma unroll
    for (int vi=0;vi<2;vi++)
        #pragma unroll
        for (int j=0;j<4;j++) acc[vi][j] = 0ull;

    for (int kc=0; kc<8; kc++){
        int k0 = kc*64;
        #pragma unroll
        for (int it=0; it<8; it++){
            int lin = it*256 + tid;
            int row = lin >> 4;
            int cg  = lin & 15;
            int v = v0 + row;
            float4 w4 = (v < V) ? *(const float4*)(W2 + (long)v*D + k0 + cg*4)
                                : make_float4(0.f,0.f,0.f,0.f);
            float* dst = sW + row*65 + cg*4;
            dst[0]=w4.x; dst[1]=w4.y; dst[2]=w4.z; dst[3]=w4.w;
        }
        #pragma unroll
        for (int it=0; it<4; it++){
            int lin = it*256 + tid;
            int bp = lin >> 6; int kk = lin & 63;
            sH[lin] = pack2(g_h[(bp*2)*D + k0+kk], g_h[(bp*2+1)*D + k0+kk]);
        }
        __syncthreads();
        #pragma unroll 8
        for (int k=0;k<64;k++){
            float w0 = sW[vl*65 + k];
            float w1 = sW[(vl+1)*65 + k];
            unsigned long long ww0 = pack2(w0,w0), ww1 = pack2(w1,w1);
            #pragma unroll
            for (int j=0;j<4;j++){
                unsigned long long hp = sH[(bg*4+j)*64 + k];
                fma2(acc[0][j], ww0, hp, acc[0][j]);
                fma2(acc[1][j], ww1, hp, acc[1][j]);
            }
        }
        __syncthreads();
    }
    #pragma unroll
    for (int vi=0; vi<2; vi++){
        int v = v0 + vl + vi;
        if (v >= V) continue;
        float bias = b2[v];
        #pragma unroll
        for (int j=0;j<4;j++){
            float lo, hi; unpack2(lo, hi, acc[vi][j]);
            int bb0 = (bg*4+j)*2;
            g_logits[(long)bb0*V + v]     = lo + bias;
            g_logits[(long)(bb0+1)*V + v] = hi + bias;
        }
    }
}

// ---------------- K7: per-row softmax stats over V ----------------
__global__ void k_red(){
    int b = blockIdx.x, tid = threadIdx.x;
    __shared__ float sm[256];
    const float* L = g_logits + (long)b*V;
    float m = -1e30f;
    for (int v=tid; v<V; v+=256) m = fmaxf(m, L[v]);
    sm[tid]=m; __syncthreads();
    for (int o=128;o;o>>=1){ if (tid<o) sm[tid]=fmaxf(sm[tid],sm[tid+o]); __syncthreads(); }
    m = sm[0]; __syncthreads();
    float s=0.f;
    for (int v=tid; v<V; v+=256) s += expf(L[v]-m);
    sm[tid]=s; __syncthreads();
    for (int o=128;o;o>>=1){ if (tid<o) sm[tid]+=sm[tid+o]; __syncthreads(); }
    if (!tid){ g_m[b]=m; g_inv_s[b] = 1.f/sm[0]; }
}

// ---------------- K8: vocab_dist ----------------
__global__ void k_soft(float* __restrict__ o_vocab){
    long i = (long)blockIdx.x*256 + threadIdx.x;
    if (i >= (long)B*V) return;
    int b = (int)(i / V);
    o_vocab[i] = expf(g_logits[i] - g_m[b]) * g_inv_s[b];
}

// ---------------- launch ----------------
extern "C" void kernel_launch(void* const* d_in, const int* in_sizes, int n_in,
                              void* d_out, int out_size){
    const float* tf    = (const float*)d_in[0];
    const float* enc   = (const float*)d_in[2];
    const float* umask = (const float*)d_in[3];
    const float* tok   = (const float*)d_in[4];
    const float* tmask = (const float*)d_in[5];
    const float* cov   = (const float*)d_in[6];
    const float* tcov  = (const float*)d_in[7];
    const float* ua_Wp = (const float*)d_in[8];
    const float* ua_bp = (const float*)d_in[9];
    const float* ua_v  = (const float*)d_in[10];
    const float* ua_wc = (const float*)d_in[11];
    const float* ta_Wp = (const float*)d_in[12];
    const float* ta_bp = (const float*)d_in[13];
    const float* ta_v  = (const float*)d_in[14];
    const float* ta_wc = (const float*)d_in[15];
    const float* pgen_W= (const float*)d_in[16];
    const float* pgen_b= (const float*)d_in[17];
    const float* W1    = (const float*)d_in[18];
    const float* b1    = (const float*)d_in[19];
    const float* W2    = (const float*)d_in[20];
    const float* b2    = (const float*)d_in[21];
    const float* ln_g  = (const float*)d_in[22];
    const float* ln_b  = (const float*)d_in[23];

    float* out = (float*)d_out;
    float* o_vocab = out;                          // B*V
    float* o_tattn = o_vocab + (long)B*V;          // B*TK
    float* o_pgen  = o_tattn + B*TK;               // B
    float* o_ucov  = o_pgen + B;                   // B*U
    float* o_ntc   = o_ucov + B*U;                 // U*B*TK
    float* o_uidx  = o_ntc + (long)U*B*TK;         // B

    k_ln   <<<B, 256>>>(tf, ln_g, ln_b);
    k_proj <<<dim3(D/8, B, 2), 256>>>(ua_Wp, ua_bp, ta_Wp, ta_bp);
    k_uatt <<<B, 256>>>(enc, umask, cov, ua_wc, ua_v, pgen_W, pgen_b,
                        o_ucov, o_pgen, o_uidx);
    k_tatt <<<dim3(U, B), 256>>>(tok, tmask, tcov, ta_wc, ta_v, o_ntc, o_tattn);
    k_h    <<<dim3(D/8, B), 256>>>(W1, b1);
    k_vocab<<<(V+VT-1)/VT, 256>>>(W2, b2);
    k_red  <<<B, 256>>>();
    k_soft <<<(int)(((long)B*V + 255)/256), 256>>>(o_vocab);
}